// round 1
// baseline (speedup 1.0000x reference)
#include <cuda_runtime.h>
#include <math.h>

// Problem constants
#define D_MODEL 1024
#define NH      16
#define DHEAD   64
#define BATCH   4
#define SEQ     1024
#define MROWS   (BATCH * SEQ)   // 4096

// ---------------------------------------------------------------------------
// Scratch (static device globals — no allocation allowed)
// ---------------------------------------------------------------------------
__device__ float g_q[(size_t)MROWS * D_MODEL];
__device__ float g_k[(size_t)MROWS * D_MODEL];
__device__ float g_v[(size_t)MROWS * D_MODEL];
__device__ float g_o[(size_t)MROWS * D_MODEL];

// ---------------------------------------------------------------------------
// GEMM: C[M,N] = A[M,K] @ W[K,N] + bias[N]
// 128x128 block tile, BK=16, 256 threads, 8x8 per-thread micro-tile.
// ---------------------------------------------------------------------------
#define BM 128
#define BN 128
#define BK 16
#define TM 8
#define TN 8

__global__ __launch_bounds__(256)
void gemm_bias_kernel(const float* __restrict__ A,
                      const float* __restrict__ W,
                      const float* __restrict__ bias,
                      float* __restrict__ C,
                      int M, int N, int K)
{
    __shared__ float As[BK][BM];      // A tile, transposed for vector reads
    __shared__ float Bs[BK][BN];

    const int tid = threadIdx.x;
    const int bm  = blockIdx.y * BM;
    const int bn  = blockIdx.x * BN;

    const int tx = tid % 16;          // column group (16 * TN = 128)
    const int ty = tid / 16;          // row group    (16 * TM = 128)

    float acc[TM][TN];
    #pragma unroll
    for (int i = 0; i < TM; i++)
        #pragma unroll
        for (int j = 0; j < TN; j++)
            acc[i][j] = 0.0f;

    for (int k0 = 0; k0 < K; k0 += BK) {
        // Load A tile: BM x BK = 2048 floats = 512 float4, 2 per thread.
        #pragma unroll
        for (int i = 0; i < 2; i++) {
            int idx = tid + i * 256;          // 0..511
            int row = idx >> 2;               // 0..127
            int c4  = idx & 3;                // float4 within the 16-wide row
            float4 v = *(const float4*)&A[(size_t)(bm + row) * K + k0 + c4 * 4];
            As[c4 * 4 + 0][row] = v.x;
            As[c4 * 4 + 1][row] = v.y;
            As[c4 * 4 + 2][row] = v.z;
            As[c4 * 4 + 3][row] = v.w;
        }
        // Load B tile: BK x BN = 2048 floats = 512 float4, 2 per thread.
        #pragma unroll
        for (int i = 0; i < 2; i++) {
            int idx = tid + i * 256;
            int r   = idx >> 5;               // 0..15
            int c4  = idx & 31;               // 32 float4 per row
            float4 v = *(const float4*)&W[(size_t)(k0 + r) * N + bn + c4 * 4];
            *(float4*)&Bs[r][c4 * 4] = v;
        }
        __syncthreads();

        #pragma unroll
        for (int kk = 0; kk < BK; kk++) {
            float a[TM], b[TN];
            #pragma unroll
            for (int i = 0; i < TM; i += 4)
                *(float4*)&a[i] = *(const float4*)&As[kk][ty * TM + i];
            #pragma unroll
            for (int j = 0; j < TN; j += 4)
                *(float4*)&b[j] = *(const float4*)&Bs[kk][tx * TN + j];
            #pragma unroll
            for (int i = 0; i < TM; i++)
                #pragma unroll
                for (int j = 0; j < TN; j++)
                    acc[i][j] = fmaf(a[i], b[j], acc[i][j]);
        }
        __syncthreads();
    }

    // Epilogue: add bias, store.
    #pragma unroll
    for (int i = 0; i < TM; i++) {
        int row = bm + ty * TM + i;
        #pragma unroll
        for (int j = 0; j < TN; j += 4) {
            int col = bn + tx * TN + j;
            float4 v;
            v.x = acc[i][j + 0] + bias[col + 0];
            v.y = acc[i][j + 1] + bias[col + 1];
            v.z = acc[i][j + 2] + bias[col + 2];
            v.w = acc[i][j + 3] + bias[col + 3];
            *(float4*)&C[(size_t)row * N + col] = v;
        }
    }
}

// ---------------------------------------------------------------------------
// Flash-attention (fp32). One CTA = 64 query rows of one (b, h).
// One thread = one query row; K/V 64x64 tiles staged in shared memory.
// Online softmax with chunked (16-wide) score computation to keep p[] in regs.
// ---------------------------------------------------------------------------
#define KROW 68   // padded row stride (floats) for K/V tiles

__global__ __launch_bounds__(64)
void attn_kernel(const float* __restrict__ Q,
                 const float* __restrict__ K,
                 const float* __restrict__ V,
                 float* __restrict__ O)
{
    __shared__ float Ks[64][KROW];
    __shared__ float Vs[64][KROW];

    const int b  = blockIdx.z;
    const int h  = blockIdx.y;
    const int qr = blockIdx.x * 64 + threadIdx.x;   // this thread's query row
    const float scale = 0.125f;                     // 1/sqrt(64)

    // Load q row into registers (pre-scaled).
    float q[DHEAD];
    {
        const float4* qp = (const float4*)&Q[((size_t)(b * SEQ + qr)) * D_MODEL + h * DHEAD];
        #pragma unroll
        for (int d4 = 0; d4 < DHEAD / 4; d4++) {
            float4 v = qp[d4];
            q[4 * d4 + 0] = v.x * scale;
            q[4 * d4 + 1] = v.y * scale;
            q[4 * d4 + 2] = v.z * scale;
            q[4 * d4 + 3] = v.w * scale;
        }
    }

    float out[DHEAD];
    #pragma unroll
    for (int d = 0; d < DHEAD; d++) out[d] = 0.0f;
    float m = -INFINITY;
    float l = 0.0f;

    for (int kt = 0; kt < SEQ / 64; kt++) {
        // Each thread loads one K row and one V row of the tile (contiguous 256B).
        {
            const size_t rbase = ((size_t)(b * SEQ + kt * 64 + threadIdx.x)) * D_MODEL + h * DHEAD;
            const float4* kp = (const float4*)&K[rbase];
            const float4* vp = (const float4*)&V[rbase];
            #pragma unroll
            for (int d4 = 0; d4 < DHEAD / 4; d4++) {
                *(float4*)&Ks[threadIdx.x][d4 * 4] = kp[d4];
                *(float4*)&Vs[threadIdx.x][d4 * 4] = vp[d4];
            }
        }
        __syncthreads();

        // Process the 64 keys in chunks of 16 (keeps p[] in registers).
        for (int jc = 0; jc < 4; jc++) {
            float p[16];
            float cmax = -INFINITY;
            #pragma unroll
            for (int jj = 0; jj < 16; jj++) {
                const int j = jc * 16 + jj;
                const float4* kr = (const float4*)&Ks[j][0];
                float s = 0.0f;
                #pragma unroll
                for (int d4 = 0; d4 < DHEAD / 4; d4++) {
                    float4 kv = kr[d4];
                    s = fmaf(q[4 * d4 + 0], kv.x, s);
                    s = fmaf(q[4 * d4 + 1], kv.y, s);
                    s = fmaf(q[4 * d4 + 2], kv.z, s);
                    s = fmaf(q[4 * d4 + 3], kv.w, s);
                }
                p[jj] = s;
                cmax = fmaxf(cmax, s);
            }
            if (cmax > m) {
                const float corr = __expf(m - cmax);   // exp(-inf)=0 handles first chunk
                l *= corr;
                #pragma unroll
                for (int d = 0; d < DHEAD; d++) out[d] *= corr;
                m = cmax;
            }
            #pragma unroll
            for (int jj = 0; jj < 16; jj++) {
                const int j = jc * 16 + jj;
                const float e = __expf(p[jj] - m);
                l += e;
                const float4* vr = (const float4*)&Vs[j][0];
                #pragma unroll
                for (int d4 = 0; d4 < DHEAD / 4; d4++) {
                    float4 vv = vr[d4];
                    out[4 * d4 + 0] = fmaf(e, vv.x, out[4 * d4 + 0]);
                    out[4 * d4 + 1] = fmaf(e, vv.y, out[4 * d4 + 1]);
                    out[4 * d4 + 2] = fmaf(e, vv.z, out[4 * d4 + 2]);
                    out[4 * d4 + 3] = fmaf(e, vv.w, out[4 * d4 + 3]);
                }
            }
        }
        __syncthreads();
    }

    const float inv = 1.0f / l;
    float4* op = (float4*)&O[((size_t)(b * SEQ + qr)) * D_MODEL + h * DHEAD];
    #pragma unroll
    for (int d4 = 0; d4 < DHEAD / 4; d4++) {
        float4 v;
        v.x = out[4 * d4 + 0] * inv;
        v.y = out[4 * d4 + 1] * inv;
        v.z = out[4 * d4 + 2] * inv;
        v.w = out[4 * d4 + 3] * inv;
        op[d4] = v;
    }
}

// ---------------------------------------------------------------------------
// Launch
// ---------------------------------------------------------------------------
extern "C" void kernel_launch(void* const* d_in, const int* in_sizes, int n_in,
                              void* d_out, int out_size)
{
    const float* queries = (const float*)d_in[0];
    const float* keys    = (const float*)d_in[1];
    const float* values  = (const float*)d_in[2];
    const float* Wq      = (const float*)d_in[3];
    const float* bq      = (const float*)d_in[4];
    const float* Wk      = (const float*)d_in[5];
    const float* bk      = (const float*)d_in[6];
    const float* Wv      = (const float*)d_in[7];
    const float* bv      = (const float*)d_in[8];
    const float* Wo      = (const float*)d_in[9];
    const float* bo      = (const float*)d_in[10];
    float* out = (float*)d_out;

    float *q, *k, *v, *o;
    cudaGetSymbolAddress((void**)&q, g_q);
    cudaGetSymbolAddress((void**)&k, g_k);
    cudaGetSymbolAddress((void**)&v, g_v);
    cudaGetSymbolAddress((void**)&o, g_o);

    const dim3 gemm_grid(D_MODEL / BN, MROWS / BM);   // (8, 32)
    const dim3 gemm_block(256);

    gemm_bias_kernel<<<gemm_grid, gemm_block>>>(queries, Wq, bq, q, MROWS, D_MODEL, D_MODEL);
    gemm_bias_kernel<<<gemm_grid, gemm_block>>>(keys,    Wk, bk, k, MROWS, D_MODEL, D_MODEL);
    gemm_bias_kernel<<<gemm_grid, gemm_block>>>(values,  Wv, bv, v, MROWS, D_MODEL, D_MODEL);

    attn_kernel<<<dim3(SEQ / 64, NH, BATCH), 64>>>(q, k, v, o);

    gemm_bias_kernel<<<gemm_grid, gemm_block>>>(o, Wo, bo, out, MROWS, D_MODEL, D_MODEL);
}

// round 2
// speedup vs baseline: 3.3260x; 3.3260x over previous
#include <cuda_runtime.h>
#include <cuda_bf16.h>
#include <math.h>
#include <stdint.h>

#define D_MODEL 1024
#define NH      16
#define DHEAD   64
#define BATCH   4
#define SEQ     1024
#define MROWS   (BATCH * SEQ)   // 4096

// ---------------------------------------------------------------------------
// Scratch (static device globals — no allocation allowed)
// ---------------------------------------------------------------------------
__device__ float g_q[(size_t)MROWS * D_MODEL];
__device__ float g_k[(size_t)MROWS * D_MODEL];
__device__ float g_v[(size_t)MROWS * D_MODEL];
__device__ float g_o[(size_t)MROWS * D_MODEL];

// ---------------------------------------------------------------------------
// Helpers
// ---------------------------------------------------------------------------
__device__ __forceinline__ uint32_t smem_u32(const void* p) {
    return (uint32_t)__cvta_generic_to_shared(p);
}

__device__ __forceinline__ void ldsm_x4(uint32_t addr, uint32_t& r0, uint32_t& r1,
                                        uint32_t& r2, uint32_t& r3) {
    asm volatile("ldmatrix.sync.aligned.m8n8.x4.shared.b16 {%0,%1,%2,%3}, [%4];"
                 : "=r"(r0), "=r"(r1), "=r"(r2), "=r"(r3) : "r"(addr));
}
__device__ __forceinline__ void ldsm_x4_t(uint32_t addr, uint32_t& r0, uint32_t& r1,
                                          uint32_t& r2, uint32_t& r3) {
    asm volatile("ldmatrix.sync.aligned.m8n8.x4.trans.shared.b16 {%0,%1,%2,%3}, [%4];"
                 : "=r"(r0), "=r"(r1), "=r"(r2), "=r"(r3) : "r"(addr));
}

__device__ __forceinline__ void mma16816(float c[4], const uint32_t a[4], const uint32_t b[2]) {
    asm volatile(
        "mma.sync.aligned.m16n8k16.row.col.f32.bf16.bf16.f32 "
        "{%0,%1,%2,%3}, {%4,%5,%6,%7}, {%8,%9}, {%0,%1,%2,%3};"
        : "+f"(c[0]), "+f"(c[1]), "+f"(c[2]), "+f"(c[3])
        : "r"(a[0]), "r"(a[1]), "r"(a[2]), "r"(a[3]), "r"(b[0]), "r"(b[1]));
}

// Split fp32 pair into packed bf16 (hi) + packed bf16 residual (lo).
__device__ __forceinline__ void split_pack(float x, float y, uint32_t& hi, uint32_t& lo) {
    __nv_bfloat16 xh = __float2bfloat16_rn(x);
    __nv_bfloat16 yh = __float2bfloat16_rn(y);
    __nv_bfloat162 h2; h2.x = xh; h2.y = yh;
    hi = *reinterpret_cast<uint32_t*>(&h2);
    float xl = x - __bfloat162float(xh);
    float yl = y - __bfloat162float(yh);
    __nv_bfloat162 l2 = __floats2bfloat162_rn(xl, yl);
    lo = *reinterpret_cast<uint32_t*>(&l2);
}

// ---------------------------------------------------------------------------
// GEMM: C[M,N] = A[M,K] @ W[K,N] + bias, bf16-split tensor cores.
// Block tile 128x128, k-tile 32. 8 warps, warp tile 64x32.
// ---------------------------------------------------------------------------
#define GBM 128
#define GBN 128
#define GBK 32
#define ASTR 40    // bf16 elements per A smem row (pad)
#define BSTR 136   // bf16 elements per B smem row (pad)

__global__ __launch_bounds__(256)
void gemm_bias_tc(const float* __restrict__ A, const float* __restrict__ W,
                  const float* __restrict__ bias, float* __restrict__ C,
                  int M, int N, int K)
{
    __shared__ __align__(16) __nv_bfloat16 Ah[GBM][ASTR];
    __shared__ __align__(16) __nv_bfloat16 Al[GBM][ASTR];
    __shared__ __align__(16) __nv_bfloat16 Bh[GBK][BSTR];
    __shared__ __align__(16) __nv_bfloat16 Bl[GBK][BSTR];

    const int tid  = threadIdx.x;
    const int lane = tid & 31;
    const int warp = tid >> 5;
    const int g    = lane >> 2;
    const int tig  = lane & 3;
    const int wm   = (warp >> 2) * 64;   // warp row offset in block
    const int wn   = (warp & 3) * 32;    // warp col offset in block
    const int bm   = blockIdx.y * GBM;
    const int bn   = blockIdx.x * GBN;

    // ldmatrix per-lane offsets
    const int lm_r = (lane & 7) + ((lane >> 3) & 1) * 8;  // row within 16
    const int lm_c = (lane >> 4) * 8;                     // col half

    float acc[4][4][4];
    #pragma unroll
    for (int i = 0; i < 4; i++)
        #pragma unroll
        for (int j = 0; j < 4; j++)
            #pragma unroll
            for (int t = 0; t < 4; t++) acc[i][j][t] = 0.0f;

    for (int k0 = 0; k0 < K; k0 += GBK) {
        // Load A tile 128x32 fp32, split to bf16 hi/lo.
        #pragma unroll
        for (int i = 0; i < 4; i++) {
            int idx = tid + i * 256;          // 0..1023
            int row = idx >> 3;               // 0..127
            int kk  = (idx & 7) * 4;
            float4 v = *(const float4*)&A[(size_t)(bm + row) * K + k0 + kk];
            uint32_t h0, l0, h1, l1;
            split_pack(v.x, v.y, h0, l0);
            split_pack(v.z, v.w, h1, l1);
            *(uint2*)&Ah[row][kk] = make_uint2(h0, h1);
            *(uint2*)&Al[row][kk] = make_uint2(l0, l1);
        }
        // Load B tile 32x128 fp32 ([k][n], n contiguous), split.
        #pragma unroll
        for (int i = 0; i < 4; i++) {
            int idx = tid + i * 256;
            int row = idx >> 5;               // 0..31 (k)
            int nn  = (idx & 31) * 4;
            float4 v = *(const float4*)&W[(size_t)(k0 + row) * N + bn + nn];
            uint32_t h0, l0, h1, l1;
            split_pack(v.x, v.y, h0, l0);
            split_pack(v.z, v.w, h1, l1);
            *(uint2*)&Bh[row][nn] = make_uint2(h0, h1);
            *(uint2*)&Bl[row][nn] = make_uint2(l0, l1);
        }
        __syncthreads();

        #pragma unroll
        for (int ks = 0; ks < 2; ks++) {
            uint32_t ah[4][4], al[4][4], bh[4][2], bl[4][2];
            #pragma unroll
            for (int i = 0; i < 4; i++) {
                uint32_t ad = smem_u32(&Ah[wm + i * 16 + lm_r][ks * 16 + lm_c]);
                ldsm_x4(ad, ah[i][0], ah[i][1], ah[i][2], ah[i][3]);
                uint32_t ad2 = smem_u32(&Al[wm + i * 16 + lm_r][ks * 16 + lm_c]);
                ldsm_x4(ad2, al[i][0], al[i][1], al[i][2], al[i][3]);
            }
            #pragma unroll
            for (int j2 = 0; j2 < 2; j2++) {
                uint32_t bd = smem_u32(&Bh[ks * 16 + lm_r][wn + j2 * 16 + lm_c]);
                ldsm_x4_t(bd, bh[2 * j2][0], bh[2 * j2][1], bh[2 * j2 + 1][0], bh[2 * j2 + 1][1]);
                uint32_t bd2 = smem_u32(&Bl[ks * 16 + lm_r][wn + j2 * 16 + lm_c]);
                ldsm_x4_t(bd2, bl[2 * j2][0], bl[2 * j2][1], bl[2 * j2 + 1][0], bl[2 * j2 + 1][1]);
            }
            // hi*hi, hi*lo, lo*hi
            #pragma unroll
            for (int i = 0; i < 4; i++)
                #pragma unroll
                for (int j = 0; j < 4; j++) mma16816(acc[i][j], ah[i], bh[j]);
            #pragma unroll
            for (int i = 0; i < 4; i++)
                #pragma unroll
                for (int j = 0; j < 4; j++) mma16816(acc[i][j], ah[i], bl[j]);
            #pragma unroll
            for (int i = 0; i < 4; i++)
                #pragma unroll
                for (int j = 0; j < 4; j++) mma16816(acc[i][j], al[i], bh[j]);
        }
        __syncthreads();
    }

    // Epilogue: bias + store.
    #pragma unroll
    for (int i = 0; i < 4; i++) {
        int r0 = bm + wm + i * 16 + g;
        #pragma unroll
        for (int j = 0; j < 4; j++) {
            int c = bn + wn + j * 8 + tig * 2;
            float b0 = bias[c], b1 = bias[c + 1];
            float2 v0 = make_float2(acc[i][j][0] + b0, acc[i][j][1] + b1);
            float2 v1 = make_float2(acc[i][j][2] + b0, acc[i][j][3] + b1);
            *(float2*)&C[(size_t)r0 * N + c]       = v0;
            *(float2*)&C[(size_t)(r0 + 8) * N + c] = v1;
        }
    }
}

// ---------------------------------------------------------------------------
// Flash attention, bf16-split tensor cores.
// CTA: 128 q-rows of one (b,h). 8 warps (16 rows each). Sk tiles of 64.
// ---------------------------------------------------------------------------
#define QBLK 128
#define KBLK 64
#define KSTR 72   // padded row stride (bf16 elements)

__global__ __launch_bounds__(256)
void attn_tc(const float* __restrict__ Q, const float* __restrict__ K,
             const float* __restrict__ V, float* __restrict__ O)
{
    // Q region (36864 B) is reused as K/V region (36864 B) after fragment load.
    __shared__ __align__(16) __nv_bfloat16 sm[2 * QBLK * KSTR];
    __nv_bfloat16 (*Qh)[KSTR] = (__nv_bfloat16(*)[KSTR])sm;
    __nv_bfloat16 (*Ql)[KSTR] = Qh + QBLK;
    __nv_bfloat16 (*Kh)[KSTR] = (__nv_bfloat16(*)[KSTR])sm;
    __nv_bfloat16 (*Kl)[KSTR] = Kh + KBLK;
    __nv_bfloat16 (*Vh)[KSTR] = Kl + KBLK;
    __nv_bfloat16 (*Vl)[KSTR] = Vh + KBLK;

    const int tid  = threadIdx.x;
    const int lane = tid & 31;
    const int warp = tid >> 5;
    const int g    = lane >> 2;
    const int tig  = lane & 3;
    const int lm_r = (lane & 7) + ((lane >> 3) & 1) * 8;
    const int lm_c = (lane >> 4) * 8;

    const int b  = blockIdx.z;
    const int h  = blockIdx.y;
    const int q0 = blockIdx.x * QBLK;
    const size_t qbase = ((size_t)(b * SEQ + q0)) * D_MODEL + h * DHEAD;

    // Phase 1: load + scale + split Q block (128x64).
    #pragma unroll
    for (int i = 0; i < 8; i++) {
        int idx = tid + i * 256;          // 0..2047
        int row = idx >> 4;               // 0..127
        int d   = (idx & 15) * 4;
        float4 v = *(const float4*)&Q[qbase + (size_t)row * D_MODEL + d];
        v.x *= 0.125f; v.y *= 0.125f; v.z *= 0.125f; v.w *= 0.125f;
        uint32_t h0, l0, h1, l1;
        split_pack(v.x, v.y, h0, l0);
        split_pack(v.z, v.w, h1, l1);
        *(uint2*)&Qh[row][d] = make_uint2(h0, h1);
        *(uint2*)&Ql[row][d] = make_uint2(l0, l1);
    }
    __syncthreads();

    // Q fragments (held in registers for the whole kernel).
    uint32_t qh[4][4], ql[4][4];
    #pragma unroll
    for (int ks = 0; ks < 4; ks++) {
        uint32_t ad = smem_u32(&Qh[warp * 16 + lm_r][ks * 16 + lm_c]);
        ldsm_x4(ad, qh[ks][0], qh[ks][1], qh[ks][2], qh[ks][3]);
        uint32_t ad2 = smem_u32(&Ql[warp * 16 + lm_r][ks * 16 + lm_c]);
        ldsm_x4(ad2, ql[ks][0], ql[ks][1], ql[ks][2], ql[ks][3]);
    }
    __syncthreads();   // Q smem region now free for K/V

    float out[8][4];
    #pragma unroll
    for (int j = 0; j < 8; j++)
        #pragma unroll
        for (int t = 0; t < 4; t++) out[j][t] = 0.0f;
    float mrow[2] = {-INFINITY, -INFINITY};
    float lrow[2] = {0.0f, 0.0f};

    for (int kt = 0; kt < SEQ / KBLK; kt++) {
        const size_t kbase = ((size_t)(b * SEQ + kt * KBLK)) * D_MODEL + h * DHEAD;
        // Load K and V tiles (64x64 each), split to bf16 hi/lo.
        #pragma unroll
        for (int i = 0; i < 4; i++) {
            int idx = tid + i * 256;      // 0..1023
            int row = idx >> 4;           // 0..63
            int d   = (idx & 15) * 4;
            float4 kv = *(const float4*)&K[kbase + (size_t)row * D_MODEL + d];
            uint32_t h0, l0, h1, l1;
            split_pack(kv.x, kv.y, h0, l0);
            split_pack(kv.z, kv.w, h1, l1);
            *(uint2*)&Kh[row][d] = make_uint2(h0, h1);
            *(uint2*)&Kl[row][d] = make_uint2(l0, l1);
            float4 vv = *(const float4*)&V[kbase + (size_t)row * D_MODEL + d];
            split_pack(vv.x, vv.y, h0, l0);
            split_pack(vv.z, vv.w, h1, l1);
            *(uint2*)&Vh[row][d] = make_uint2(h0, h1);
            *(uint2*)&Vl[row][d] = make_uint2(l0, l1);
        }
        __syncthreads();

        // ---- QK^T: scores s[8 tiles][4] for 16 rows x 64 keys per warp ----
        float s[8][4];
        #pragma unroll
        for (int j = 0; j < 8; j++)
            #pragma unroll
            for (int t = 0; t < 4; t++) s[j][t] = 0.0f;

        #pragma unroll
        for (int ks = 0; ks < 4; ks++) {
            uint32_t bh[8][2], bl[8][2];
            const int dd = ks * 16 + tig * 2;
            #pragma unroll
            for (int j = 0; j < 8; j++) {
                int key = j * 8 + g;
                bh[j][0] = *(const uint32_t*)&Kh[key][dd];
                bh[j][1] = *(const uint32_t*)&Kh[key][dd + 8];
                bl[j][0] = *(const uint32_t*)&Kl[key][dd];
                bl[j][1] = *(const uint32_t*)&Kl[key][dd + 8];
            }
            #pragma unroll
            for (int j = 0; j < 8; j++) mma16816(s[j], qh[ks], bh[j]);
            #pragma unroll
            for (int j = 0; j < 8; j++) mma16816(s[j], qh[ks], bl[j]);
            #pragma unroll
            for (int j = 0; j < 8; j++) mma16816(s[j], ql[ks], bh[j]);
        }

        // ---- online softmax (2 rows per thread) ----
        #pragma unroll
        for (int r = 0; r < 2; r++) {
            float mx = -INFINITY;
            #pragma unroll
            for (int j = 0; j < 8; j++) {
                mx = fmaxf(mx, s[j][2 * r]);
                mx = fmaxf(mx, s[j][2 * r + 1]);
            }
            mx = fmaxf(mx, __shfl_xor_sync(0xFFFFFFFFu, mx, 1));
            mx = fmaxf(mx, __shfl_xor_sync(0xFFFFFFFFu, mx, 2));
            float newm = fmaxf(mrow[r], mx);
            float corr = __expf(mrow[r] - newm);
            mrow[r] = newm;
            float lsum = 0.0f;
            #pragma unroll
            for (int j = 0; j < 8; j++) {
                float e0 = __expf(s[j][2 * r]     - newm);
                float e1 = __expf(s[j][2 * r + 1] - newm);
                s[j][2 * r] = e0; s[j][2 * r + 1] = e1;
                lsum += e0 + e1;
                out[j][2 * r]     *= corr;
                out[j][2 * r + 1] *= corr;
            }
            lrow[r] = lrow[r] * corr + lsum;
        }

        // ---- P @ V ----
        #pragma unroll
        for (int ss = 0; ss < 4; ss++) {
            uint32_t ph[4], pl[4];
            split_pack(s[2 * ss][0],     s[2 * ss][1],     ph[0], pl[0]);
            split_pack(s[2 * ss][2],     s[2 * ss][3],     ph[1], pl[1]);
            split_pack(s[2 * ss + 1][0], s[2 * ss + 1][1], ph[2], pl[2]);
            split_pack(s[2 * ss + 1][2], s[2 * ss + 1][3], ph[3], pl[3]);

            uint32_t vh[8][2], vl[8][2];
            #pragma unroll
            for (int j2 = 0; j2 < 4; j2++) {
                int row = ss * 16 + lm_r;
                int col = j2 * 16 + lm_c;
                uint32_t vd = smem_u32(&Vh[row][col]);
                ldsm_x4_t(vd, vh[2 * j2][0], vh[2 * j2][1], vh[2 * j2 + 1][0], vh[2 * j2 + 1][1]);
                uint32_t vd2 = smem_u32(&Vl[row][col]);
                ldsm_x4_t(vd2, vl[2 * j2][0], vl[2 * j2][1], vl[2 * j2 + 1][0], vl[2 * j2 + 1][1]);
            }
            #pragma unroll
            for (int j = 0; j < 8; j++) mma16816(out[j], ph, vh[j]);
            #pragma unroll
            for (int j = 0; j < 8; j++) mma16816(out[j], ph, vl[j]);
            #pragma unroll
            for (int j = 0; j < 8; j++) mma16816(out[j], pl, vh[j]);
        }
        __syncthreads();
    }

    // Final: cross-lane l reduction, normalize, store.
    #pragma unroll
    for (int r = 0; r < 2; r++) {
        lrow[r] += __shfl_xor_sync(0xFFFFFFFFu, lrow[r], 1);
        lrow[r] += __shfl_xor_sync(0xFFFFFFFFu, lrow[r], 2);
    }
    const float inv0 = 1.0f / lrow[0];
    const float inv1 = 1.0f / lrow[1];
    const int row0 = q0 + warp * 16 + g;
    #pragma unroll
    for (int j = 0; j < 8; j++) {
        int d = j * 8 + tig * 2;
        size_t addr = ((size_t)(b * SEQ + row0)) * D_MODEL + h * DHEAD + d;
        *(float2*)&O[addr]               = make_float2(out[j][0] * inv0, out[j][1] * inv0);
        *(float2*)&O[addr + 8 * D_MODEL] = make_float2(out[j][2] * inv1, out[j][3] * inv1);
    }
}

// ---------------------------------------------------------------------------
// Launch
// ---------------------------------------------------------------------------
extern "C" void kernel_launch(void* const* d_in, const int* in_sizes, int n_in,
                              void* d_out, int out_size)
{
    const float* queries = (const float*)d_in[0];
    const float* keys    = (const float*)d_in[1];
    const float* values  = (const float*)d_in[2];
    const float* Wq      = (const float*)d_in[3];
    const float* bq      = (const float*)d_in[4];
    const float* Wk      = (const float*)d_in[5];
    const float* bk      = (const float*)d_in[6];
    const float* Wv      = (const float*)d_in[7];
    const float* bv      = (const float*)d_in[8];
    const float* Wo      = (const float*)d_in[9];
    const float* bo      = (const float*)d_in[10];
    float* out = (float*)d_out;

    float *q, *k, *v, *o;
    cudaGetSymbolAddress((void**)&q, g_q);
    cudaGetSymbolAddress((void**)&k, g_k);
    cudaGetSymbolAddress((void**)&v, g_v);
    cudaGetSymbolAddress((void**)&o, g_o);

    const dim3 gemm_grid(D_MODEL / GBN, MROWS / GBM);   // (8, 32)

    gemm_bias_tc<<<gemm_grid, 256>>>(queries, Wq, bq, q, MROWS, D_MODEL, D_MODEL);
    gemm_bias_tc<<<gemm_grid, 256>>>(keys,    Wk, bk, k, MROWS, D_MODEL, D_MODEL);
    gemm_bias_tc<<<gemm_grid, 256>>>(values,  Wv, bv, v, MROWS, D_MODEL, D_MODEL);

    attn_tc<<<dim3(SEQ / QBLK, NH, BATCH), 256>>>(q, k, v, o);

    gemm_bias_tc<<<gemm_grid, 256>>>(o, Wo, bo, out, MROWS, D_MODEL, D_MODEL);
}